// round 3
// baseline (speedup 1.0000x reference)
#include <cuda_runtime.h>
#include <math.h>

#define NN 65536
#define EE 262144
#define NPGS 8192
#define BB 8
#define NEG_INF __int_as_float(0xff800000)

// ---------------- scratch (device globals; 16B-aligned for vector casts) ----------------
__device__ __align__(16) int            g_m1[NN], g_m0[NN];
__device__ __align__(16) unsigned char  g_m2b[NN], g_m1b[NN], g_m0b[NN];
__device__ __align__(16) int   g_e0[EE], g_e1[EE], g_e2[EE];
__device__ __align__(16) int   g_s0[NN], g_s1[NN];
__device__ __align__(16) int   g_cnt[8];     // 0:nE2 1:nE1 2:nE0 3:nS0 4:nS1
__device__ __align__(16) float g_h0[NN * 128];
__device__ __align__(16) float g_h1[NN * 256];
__device__ __align__(16) float g_q[NN * 256];
__device__ __align__(16) float g_k[NN * 256];
__device__ __align__(16) float g_v[NN * 256];
__device__ __align__(16) float g_amax[NN * 4];
__device__ __align__(16) float g_asum[NN * 4];
__device__ __align__(16) float g_alpha[EE * 4];

__device__ __forceinline__ void atomicMaxF(float* a, float v) {
    if (v >= 0.0f) atomicMax((int*)a, __float_as_int(v));
    else           atomicMin((unsigned int*)a, __float_as_uint(v));
}

__device__ __forceinline__ void zero_row_h1(int n) {
    float4 z = make_float4(0.f, 0.f, 0.f, 0.f);
    float4* p = (float4*)&g_h1[n * 256];
    #pragma unroll 8
    for (int q = 0; q < 64; q++) p[q] = z;
    ((float4*)&g_amax[n * 4])[0] = make_float4(NEG_INF, NEG_INF, NEG_INF, NEG_INF);
    ((float4*)&g_asum[n * 4])[0] = z;
}
__device__ __forceinline__ void zero_row_h0(int n) {
    float4 z = make_float4(0.f, 0.f, 0.f, 0.f);
    float4* p = (float4*)&g_h0[n * 128];
    #pragma unroll 8
    for (int q = 0; q < 32; q++) p[q] = z;
}

// ---------------- 1. reset + seed (fused, arithmetic seed marking) ----------------
__global__ void k_reset(const int* __restrict__ aid) {
    __shared__ int sa[8];
    if (threadIdx.x < 8) sa[threadIdx.x] = aid[threadIdx.x];
    __syncthreads();
    int t = blockIdx.x * blockDim.x + threadIdx.x;   // 16384 threads
    {
        int base = t * 4;
        int a = sa[base >> 13];          // group of 4 stays within one 8192-page
        int4 v;
        v.x = ((base     & 8191) == a);
        v.y = (((base+1) & 8191) == a);
        v.z = (((base+2) & 8191) == a);
        v.w = (((base+3) & 8191) == a);
        ((int4*)g_m1)[t] = v;
        ((int4*)g_m0)[t] = v;
    }
    if (t < NN / 16) {
        int base = t * 16;
        int a = sa[base >> 13];
        unsigned int w[4];
        #pragma unroll
        for (int g = 0; g < 4; g++) {
            unsigned int acc = 0;
            #pragma unroll
            for (int bb = 0; bb < 4; bb++) {
                int idx = base + g * 4 + bb;
                acc |= (((idx & 8191) == a) ? 1u : 0u) << (8 * bb);
            }
            w[g] = acc;
        }
        uint4 val = make_uint4(w[0], w[1], w[2], w[3]);
        ((uint4*)g_m2b)[t] = val;
        ((uint4*)g_m1b)[t] = val;
        ((uint4*)g_m0b)[t] = val;
    }
    if (t == 0) { g_cnt[0] = 0; g_cnt[1] = 0; g_cnt[2] = 0; g_cnt[3] = 8; g_cnt[4] = 8; }
    if (t < 8) {
        int n = t * NPGS + sa[t];
        g_s0[t] = n; g_s1[t] = n;
        zero_row_h0(n);
        zero_row_h1(n);
    }
}

// ---------------- 2-4. cone scans (4 edges/thread, byte probes, zero-on-discovery) --------
__global__ void k_scan2(const int* __restrict__ src, const int* __restrict__ dst) {
    int t = blockIdx.x * blockDim.x + threadIdx.x;
    if (t >= EE / 4) return;
    int4 d4 = ((const int4*)dst)[t];
    int dd[4] = {d4.x, d4.y, d4.z, d4.w};
    #pragma unroll
    for (int j = 0; j < 4; j++) {
        if (g_m2b[dd[j]]) {
            int e = t * 4 + j;
            g_e2[atomicAdd(&g_cnt[0], 1)] = e;
            int s = src[e];
            if (atomicExch(&g_m1[s], 1) == 0) {
                g_m1b[s] = 1;
                g_s1[atomicAdd(&g_cnt[4], 1)] = s;
                zero_row_h1(s);
            }
            if (atomicExch(&g_m0[s], 1) == 0) {
                g_m0b[s] = 1;
                g_s0[atomicAdd(&g_cnt[3], 1)] = s;
                zero_row_h0(s);
            }
        }
    }
}

__global__ void k_scan1(const int* __restrict__ src, const int* __restrict__ dst) {
    int t = blockIdx.x * blockDim.x + threadIdx.x;
    if (t >= EE / 4) return;
    int4 d4 = ((const int4*)dst)[t];
    int dd[4] = {d4.x, d4.y, d4.z, d4.w};
    #pragma unroll
    for (int j = 0; j < 4; j++) {
        if (g_m1b[dd[j]]) {
            int e = t * 4 + j;
            g_e1[atomicAdd(&g_cnt[1], 1)] = e;
            int s = src[e];
            if (atomicExch(&g_m0[s], 1) == 0) {
                g_m0b[s] = 1;
                g_s0[atomicAdd(&g_cnt[3], 1)] = s;
                zero_row_h0(s);
            }
        }
    }
}

__global__ void k_scan0(const int* __restrict__ dst) {
    int t = blockIdx.x * blockDim.x + threadIdx.x;
    if (t >= EE / 4) return;
    int4 d4 = ((const int4*)dst)[t];
    int dd[4] = {d4.x, d4.y, d4.z, d4.w};
    #pragma unroll
    for (int j = 0; j < 4; j++) {
        if (g_m0b[dd[j]]) g_e0[atomicAdd(&g_cnt[2], 1)] = t * 4 + j;
    }
}

// ---------------- 5. edge MLP, 8 edges per block per weight pass ----------------
#define TE 8
__global__ void k_mlp(const float* __restrict__ x, const int* __restrict__ src,
                      const int* __restrict__ dst, const float* __restrict__ eattr,
                      const float* __restrict__ emb,
                      const float* __restrict__ w1, const float* __restrict__ b1,
                      const float* __restrict__ wh, const float* __restrict__ bh) {
    __shared__ __align__(16) float sint[52][TE];
    __shared__ __align__(16) float szt[128][TE];
    __shared__ int   ss[TE], ds[TE], sent[TE];
    __shared__ float sea[TE];
    int tid = threadIdx.x;   // 128
    int cnt = g_cnt[2];
    for (int base = blockIdx.x * TE; base < cnt; base += gridDim.x * TE) {
        int ne = min(TE, cnt - base);
        if (tid < ne) {
            int e = g_e0[base + tid];
            int s = src[e];
            ss[tid] = s; ds[tid] = dst[e]; sea[tid] = eattr[e];
            sent[tid] = (int)x[s * 36 + 35];
        }
        __syncthreads();
        for (int idx = tid; idx < 52 * TE; idx += 128) {
            int j = idx >> 3, e = idx & 7;
            float v = 0.f;
            if (e < ne) {
                if (j < 35)      v = x[ss[e] * 36 + j];
                else if (j < 51) v = emb[sent[e] * 16 + (j - 35)];
                else             v = sea[e];
            }
            sint[j][e] = v;
        }
        __syncthreads();
        float acc[TE];
        {
            float b = b1[tid];
            #pragma unroll
            for (int e = 0; e < TE; e++) acc[e] = b;
        }
        for (int j = 0; j < 52; j++) {
            float w = w1[j * 128 + tid];
            float4 a0 = *(float4*)&sint[j][0];
            float4 a1 = *(float4*)&sint[j][4];
            acc[0] += a0.x * w; acc[1] += a0.y * w; acc[2] += a0.z * w; acc[3] += a0.w * w;
            acc[4] += a1.x * w; acc[5] += a1.y * w; acc[6] += a1.z * w; acc[7] += a1.w * w;
        }
        #pragma unroll
        for (int e = 0; e < TE; e++) szt[tid][e] = fmaxf(acc[e], 0.f);
        __syncthreads();
        float acc2[TE];
        {
            float b = bh[tid];
            #pragma unroll
            for (int e = 0; e < TE; e++) acc2[e] = b;
        }
        for (int j = 0; j < 128; j++) {
            float w = wh[j * 128 + tid];
            float4 a0 = *(float4*)&szt[j][0];
            float4 a1 = *(float4*)&szt[j][4];
            acc2[0] += a0.x * w; acc2[1] += a0.y * w; acc2[2] += a0.z * w; acc2[3] += a0.w * w;
            acc2[4] += a1.x * w; acc2[5] += a1.y * w; acc2[6] += a1.z * w; acc2[7] += a1.w * w;
        }
        #pragma unroll
        for (int e = 0; e < TE; e++)
            if (e < ne) atomicAdd(&g_h0[ds[e] * 128 + tid], fmaxf(acc2[e], 0.f));
        __syncthreads();
    }
}

// ---------------- 6/10. qkv projection, 4 nodes per weight pass ----------------
template<int IND>
__global__ void k_qkv(const float* __restrict__ qw, const float* __restrict__ qb,
                      const float* __restrict__ kw, const float* __restrict__ kb,
                      const float* __restrict__ vw, const float* __restrict__ vb) {
    const float* hsrc = (IND == 128) ? g_h0 : g_h1;
    const int*   list = (IND == 128) ? g_s0 : g_s1;
    int cnt = g_cnt[(IND == 128) ? 3 : 4];
    __shared__ __align__(16) float hrt[IND][4];
    __shared__ int ns[4];
    int tid = threadIdx.x;   // 256
    for (int base = blockIdx.x * 4; base < cnt; base += gridDim.x * 4) {
        int nn = min(4, cnt - base);
        if (tid < 4) ns[tid] = list[base + min(tid, nn - 1)];
        __syncthreads();
        for (int idx = tid; idx < IND * 4; idx += 256) {
            int e = idx / IND, j = idx % IND;
            hrt[j][e] = hsrc[ns[e] * IND + j];
        }
        __syncthreads();
        float aq[4], ak[4], av[4];
        {
            float bq = qb[tid], bk = kb[tid], bv = vb[tid];
            #pragma unroll
            for (int e = 0; e < 4; e++) { aq[e] = bq; ak[e] = bk; av[e] = bv; }
        }
        for (int j = 0; j < IND; j++) {
            float wq = qw[j * 256 + tid], wk = kw[j * 256 + tid], wv = vw[j * 256 + tid];
            float4 h4 = *(float4*)&hrt[j][0];
            aq[0] += h4.x * wq; aq[1] += h4.y * wq; aq[2] += h4.z * wq; aq[3] += h4.w * wq;
            ak[0] += h4.x * wk; ak[1] += h4.y * wk; ak[2] += h4.z * wk; ak[3] += h4.w * wk;
            av[0] += h4.x * wv; av[1] += h4.y * wv; av[2] += h4.z * wv; av[3] += h4.w * wv;
        }
        #pragma unroll
        for (int e = 0; e < 4; e++) {
            if (e < nn) {
                g_q[ns[e] * 256 + tid] = aq[e];
                g_k[ns[e] * 256 + tid] = ak[e];
                g_v[ns[e] * 256 + tid] = av[e];
            }
        }
        __syncthreads();
    }
}

// ---------------- 7. layer-1 alpha + segment max ----------------
__global__ void k_amax1(const int* __restrict__ src, const int* __restrict__ dst,
                        const float* __restrict__ eattr, const float* __restrict__ ew) {
    int cnt = g_cnt[1] * 4;
    for (int t = blockIdx.x * blockDim.x + threadIdx.x; t < cnt; t += gridDim.x * blockDim.x) {
        int i = t >> 2, h = t & 3;
        int e = g_e1[i];
        int s = src[e], d = dst[e];
        float ea = eattr[e];
        const float4* qp = (const float4*)(g_q + d * 256 + h * 64);
        const float4* kp = (const float4*)(g_k + s * 256 + h * 64);
        const float4* ep = (const float4*)(ew + h * 64);
        float dot = 0.f;
        #pragma unroll
        for (int c = 0; c < 16; c++) {
            float4 q = qp[c], k = kp[c], w = ep[c];
            dot += q.x * (k.x + ea * w.x) + q.y * (k.y + ea * w.y)
                 + q.z * (k.z + ea * w.z) + q.w * (k.w + ea * w.w);
        }
        float a = dot * 0.125f;
        g_alpha[t] = a;
        atomicMaxF(&g_amax[d * 4 + h], a);
    }
}

// ---------------- 8. layer-1 exp + sum + unnormalized message (fused) ----------------
__global__ void k_msgexp1(const int* __restrict__ src, const int* __restrict__ dst,
                          const float* __restrict__ eattr, const float* __restrict__ ew) {
    int cnt = g_cnt[1];
    int tid = threadIdx.x;   // 256
    int h = tid >> 6;
    for (int i = blockIdx.x; i < cnt; i += gridDim.x) {
        int e = g_e1[i];
        int s = src[e], d = dst[e];
        float ea = eattr[e];
        float ex = expf(g_alpha[i * 4 + h] - g_amax[d * 4 + h]);
        if ((tid & 63) == 0) atomicAdd(&g_asum[d * 4 + h], ex);
        atomicAdd(&g_h1[d * 256 + tid], (g_v[s * 256 + tid] + ea * ew[tid]) * ex);
    }
}

// ---------------- 9. finalize layer 1: h1 = relu(num/sum + h0@sw + sb) ----------------
__global__ void k_fin1(const float* __restrict__ sw, const float* __restrict__ sb) {
    __shared__ float hr[128];
    int tid = threadIdx.x;   // 256
    int cnt = g_cnt[4];
    for (int i = blockIdx.x; i < cnt; i += gridDim.x) {
        int n = g_s1[i];
        if (tid < 128) hr[tid] = g_h0[n * 128 + tid];
        __syncthreads();
        int h = tid >> 6;
        float a = g_h1[n * 256 + tid] / (g_asum[n * 4 + h] + 1e-16f) + sb[tid];
        #pragma unroll 4
        for (int j = 0; j < 128; j++) a += hr[j] * sw[j * 256 + tid];
        g_h1[n * 256 + tid] = fmaxf(a, 0.f);
        __syncthreads();
    }
}

// ---------------- 11. layer-2: fully fused attention + output (8 blocks) ----------------
__global__ void k_layer2(const int* __restrict__ aid, const int* __restrict__ src,
                         const int* __restrict__ dst, const float* __restrict__ eattr,
                         const float* __restrict__ ew, const float* __restrict__ sw,
                         const float* __restrict__ sb, float* __restrict__ out) {
    __shared__ int   sd_all[256], ss_all[256];
    __shared__ float sea_all[256];
    __shared__ int   ssrc[64];
    __shared__ float seaa[64];
    __shared__ float sal[4][64];
    __shared__ float hr[256];
    __shared__ int   ne_sh;
    int b = blockIdx.x, tid = threadIdx.x;
    int n = b * NPGS + aid[b];
    int cnt = g_cnt[0]; if (cnt > 256) cnt = 256;
    if (tid < cnt) {
        int e = g_e2[tid];
        sd_all[tid] = dst[e]; ss_all[tid] = src[e]; sea_all[tid] = eattr[e];
    }
    __syncthreads();
    if (tid == 0) {   // deterministic gather of this block's edges
        int p = 0;
        for (int i = 0; i < cnt; i++)
            if ((sd_all[i] >> 13) == b && p < 64) { ssrc[p] = ss_all[i]; seaa[p] = sea_all[i]; p++; }
        ne_sh = p;
    }
    __syncthreads();
    int ne = ne_sh;
    int wid = tid >> 5, lane = tid & 31;
    for (int p = wid; p < ne * 4; p += 8) {
        int k = p >> 2, h = p & 3;
        int s = ssrc[k]; float ea = seaa[k];
        float d0 = 0.f;
        for (int c = lane; c < 64; c += 32)
            d0 += g_q[n * 256 + h * 64 + c] * (g_k[s * 256 + h * 64 + c] + ea * ew[h * 64 + c]);
        #pragma unroll
        for (int o = 16; o; o >>= 1) d0 += __shfl_xor_sync(0xffffffffu, d0, o);
        if (lane == 0) sal[h][k] = d0 * 0.125f;
    }
    __syncthreads();
    if (tid < 4) {   // per-head softmax over this block's edges (ne small)
        float m = NEG_INF;
        for (int k = 0; k < ne; k++) m = fmaxf(m, sal[tid][k]);
        float s = 0.f;
        for (int k = 0; k < ne; k++) { float ex = expf(sal[tid][k] - m); sal[tid][k] = ex; s += ex; }
        float inv = 1.f / (s + 1e-16f);
        for (int k = 0; k < ne; k++) sal[tid][k] *= inv;
    }
    __syncthreads();
    int h = tid >> 6;
    float acc = 0.f;
    for (int k = 0; k < ne; k++)
        acc += (g_v[ssrc[k] * 256 + tid] + seaa[k] * ew[tid]) * sal[h][k];
    hr[tid] = g_h1[n * 256 + tid];
    __syncthreads();
    float o = acc + sb[tid];
    #pragma unroll 4
    for (int j = 0; j < 256; j++) o += hr[j] * sw[j * 256 + tid];
    out[b * 256 + tid] = fmaxf(o, 0.f);
}

// ---------------- launch ----------------
extern "C" void kernel_launch(void* const* d_in, const int* in_sizes, int n_in,
                              void* d_out, int out_size) {
    const float* x     = (const float*)d_in[0];
    const int*   esrc  = (const int*)d_in[1];
    const int*   edst  = (const int*)d_in[2];
    const float* eattr = (const float*)d_in[3];
    const int*   aid   = (const int*)d_in[4];
    const float* emb   = (const float*)d_in[5];
    const float* w1    = (const float*)d_in[6];
    const float* b1    = (const float*)d_in[7];
    const float* wh    = (const float*)d_in[8];
    const float* bh    = (const float*)d_in[9];
    const float* q1w = (const float*)d_in[10], *q1b = (const float*)d_in[11];
    const float* k1w = (const float*)d_in[12], *k1b = (const float*)d_in[13];
    const float* v1w = (const float*)d_in[14], *v1b = (const float*)d_in[15];
    const float* e1w = (const float*)d_in[16];
    const float* s1w = (const float*)d_in[17], *s1b = (const float*)d_in[18];
    const float* q2w = (const float*)d_in[19], *q2b = (const float*)d_in[20];
    const float* k2w = (const float*)d_in[21], *k2b = (const float*)d_in[22];
    const float* v2w = (const float*)d_in[23], *v2b = (const float*)d_in[24];
    const float* e2w = (const float*)d_in[25];
    const float* s2w = (const float*)d_in[26], *s2b = (const float*)d_in[27];
    float* out = (float*)d_out;

    k_reset<<<64, 256>>>(aid);                       // 1
    k_scan2<<<256, 256>>>(esrc, edst);               // 2
    k_scan1<<<256, 256>>>(esrc, edst);               // 3
    k_scan0<<<256, 256>>>(edst);                     // 4
    k_mlp<<<128, 128>>>(x, esrc, edst, eattr, emb, w1, b1, wh, bh);   // 5
    k_qkv<128><<<64, 256>>>(q1w, q1b, k1w, k1b, v1w, v1b);            // 6
    k_amax1<<<16, 256>>>(esrc, edst, eattr, e1w);    // 7
    k_msgexp1<<<64, 256>>>(esrc, edst, eattr, e1w);  // 8
    k_fin1<<<64, 256>>>(s1w, s1b);                   // 9
    k_qkv<256><<<16, 256>>>(q2w, q2b, k2w, k2b, v2w, v2b);            // 10
    k_layer2<<<8, 256>>>(aid, esrc, edst, eattr, e2w, s2w, s2b, out); // 11
}

// round 4
// speedup vs baseline: 1.4573x; 1.4573x over previous
#include <cuda_runtime.h>
#include <math.h>

#define NN 65536
#define EE 262144
#define NPGS 8192
#define GRID 148
#define TPB 256
#define NT (GRID * TPB)
#define NEG_INF __int_as_float(0xff800000)

// ---------------- scratch (device globals; 16B-aligned for vector casts) ----------------
__device__ __align__(16) int            g_m1[NN], g_m0[NN];
__device__ __align__(16) unsigned char  g_m2b[NN], g_m1b[NN], g_m0b[NN];
__device__ __align__(16) int   g_e0[EE], g_e1[EE], g_e2[EE];
__device__ __align__(16) int   g_s0[NN], g_s1[NN];
__device__ __align__(16) int   g_cnt[8];     // 0:nE2 1:nE1 2:nE0 3:nS0 4:nS1
__device__ __align__(16) float g_h0[NN * 128];
__device__ __align__(16) float g_h1[NN * 256];
__device__ __align__(16) float g_q[NN * 256];
__device__ __align__(16) float g_k[NN * 256];
__device__ __align__(16) float g_v[NN * 256];
__device__ __align__(16) float g_amax[NN * 4];
__device__ __align__(16) float g_asum[NN * 4];
__device__ __align__(16) float g_alpha[EE * 4];

// software grid barrier state (persists across replays; generation-based, replay-invariant)
__device__ unsigned          g_bar_cnt;
__device__ volatile unsigned g_bar_gen;

__device__ __forceinline__ void gsync() {
    __syncthreads();
    if (threadIdx.x == 0) {
        __threadfence();
        unsigned gen = g_bar_gen;
        if (atomicAdd(&g_bar_cnt, 1u) == GRID - 1) {
            g_bar_cnt = 0;
            __threadfence();
            g_bar_gen = gen + 1;
        } else {
            while (g_bar_gen == gen) __nanosleep(32);
            __threadfence();
        }
    }
    __syncthreads();
}

__device__ __forceinline__ void atomicMaxF(float* a, float v) {
    if (v >= 0.0f) atomicMax((int*)a, __float_as_int(v));
    else           atomicMin((unsigned int*)a, __float_as_uint(v));
}

__device__ __forceinline__ void zero_row_h1(int n) {
    float4 z = make_float4(0.f, 0.f, 0.f, 0.f);
    float4* p = (float4*)&g_h1[n * 256];
    #pragma unroll 8
    for (int q = 0; q < 64; q++) p[q] = z;
    ((float4*)&g_amax[n * 4])[0] = make_float4(NEG_INF, NEG_INF, NEG_INF, NEG_INF);
    ((float4*)&g_asum[n * 4])[0] = z;
}
__device__ __forceinline__ void zero_row_h0(int n) {
    float4 z = make_float4(0.f, 0.f, 0.f, 0.f);
    float4* p = (float4*)&g_h0[n * 128];
    #pragma unroll 8
    for (int q = 0; q < 32; q++) p[q] = z;
}

// qkv projection phase: 4 nodes per weight pass, grid-strided over node list
template<int IND>
__device__ __forceinline__ void qkv_phase(const float* __restrict__ hsrc,
                                          const int* __restrict__ list, int cnt,
                                          const float* __restrict__ qw, const float* __restrict__ qb,
                                          const float* __restrict__ kw, const float* __restrict__ kb,
                                          const float* __restrict__ vw, const float* __restrict__ vb,
                                          float (*hrt)[4], int* ns4, int bid, int tid) {
    for (int base = bid * 4; base < cnt; base += GRID * 4) {
        int nn = min(4, cnt - base);
        if (tid < 4) ns4[tid] = list[base + min(tid, nn - 1)];
        __syncthreads();
        for (int idx = tid; idx < IND * 4; idx += TPB) {
            int e = idx / IND, j = idx % IND;
            hrt[j][e] = hsrc[ns4[e] * IND + j];
        }
        __syncthreads();
        float aq[4], ak[4], av[4];
        {
            float bq = qb[tid], bk = kb[tid], bv = vb[tid];
            #pragma unroll
            for (int e = 0; e < 4; e++) { aq[e] = bq; ak[e] = bk; av[e] = bv; }
        }
        #pragma unroll 4
        for (int j = 0; j < IND; j++) {
            float wq = qw[j * 256 + tid], wk = kw[j * 256 + tid], wv = vw[j * 256 + tid];
            float4 h4 = *(float4*)&hrt[j][0];
            aq[0] += h4.x * wq; aq[1] += h4.y * wq; aq[2] += h4.z * wq; aq[3] += h4.w * wq;
            ak[0] += h4.x * wk; ak[1] += h4.y * wk; ak[2] += h4.z * wk; ak[3] += h4.w * wk;
            av[0] += h4.x * wv; av[1] += h4.y * wv; av[2] += h4.z * wv; av[3] += h4.w * wv;
        }
        #pragma unroll
        for (int e = 0; e < 4; e++) {
            if (e < nn) {
                g_q[ns4[e] * 256 + tid] = aq[e];
                g_k[ns4[e] * 256 + tid] = ak[e];
                g_v[ns4[e] * 256 + tid] = av[e];
            }
        }
        __syncthreads();
    }
}

// ==================== single persistent megakernel ====================
__global__ void __launch_bounds__(TPB, 2)
k_mega(const float* __restrict__ x, const int* __restrict__ esrc,
       const int* __restrict__ edst, const float* __restrict__ eattr,
       const int* __restrict__ aid, const float* __restrict__ emb,
       const float* __restrict__ w1, const float* __restrict__ b1,
       const float* __restrict__ wh, const float* __restrict__ bh,
       const float* __restrict__ q1w, const float* __restrict__ q1b,
       const float* __restrict__ k1w, const float* __restrict__ k1b,
       const float* __restrict__ v1w, const float* __restrict__ v1b,
       const float* __restrict__ e1w,
       const float* __restrict__ s1w, const float* __restrict__ s1b,
       const float* __restrict__ q2w, const float* __restrict__ q2b,
       const float* __restrict__ k2w, const float* __restrict__ k2b,
       const float* __restrict__ v2w, const float* __restrict__ v2b,
       const float* __restrict__ e2w,
       const float* __restrict__ s2w, const float* __restrict__ s2b,
       float* __restrict__ out) {
    __shared__ int   sa[8];
    __shared__ __align__(16) float sint[52][8];
    __shared__ __align__(16) float szt[128][8];
    __shared__ int   ss8[8], ds8[8], sent8[8];
    __shared__ float sea8[8];
    __shared__ __align__(16) float hrt[256][4];
    __shared__ int   ns4[4];
    __shared__ float hr[256];
    __shared__ int   sd_all[256], ss_all[256];
    __shared__ float sea_all[256];
    __shared__ int   ssrc[64];
    __shared__ float seaa[64];
    __shared__ float sal[4][64];
    __shared__ int   ne_sh;

    int tid = threadIdx.x, bid = blockIdx.x;
    int gt  = bid * TPB + tid;

    if (tid < 8) sa[tid] = aid[tid];
    __syncthreads();

    // ---------- phase 0: reset + seed ----------
    if (gt < NN / 4) {
        int base = gt * 4;
        int a = sa[base >> 13];
        int4 v;
        v.x = ((base     & 8191) == a);
        v.y = (((base+1) & 8191) == a);
        v.z = (((base+2) & 8191) == a);
        v.w = (((base+3) & 8191) == a);
        ((int4*)g_m1)[gt] = v;
        ((int4*)g_m0)[gt] = v;
    }
    if (gt < NN / 16) {
        int base = gt * 16;
        int a = sa[base >> 13];
        unsigned int w[4];
        #pragma unroll
        for (int g = 0; g < 4; g++) {
            unsigned int acc = 0;
            #pragma unroll
            for (int bb = 0; bb < 4; bb++) {
                int idx = base + g * 4 + bb;
                acc |= (((idx & 8191) == a) ? 1u : 0u) << (8 * bb);
            }
            w[g] = acc;
        }
        uint4 val = make_uint4(w[0], w[1], w[2], w[3]);
        ((uint4*)g_m2b)[gt] = val;
        ((uint4*)g_m1b)[gt] = val;
        ((uint4*)g_m0b)[gt] = val;
    }
    if (gt == 0) { g_cnt[0] = 0; g_cnt[1] = 0; g_cnt[2] = 0; g_cnt[3] = 8; g_cnt[4] = 8; }
    if (gt < 8) {
        int n = gt * NPGS + sa[gt];
        g_s0[gt] = n; g_s1[gt] = n;
        zero_row_h0(n);
        zero_row_h1(n);
    }
    gsync();

    // ---------- phase 1: scan2 (E2 = dst in S2; grow S1, S0) ----------
    for (int t = gt; t < EE / 4; t += NT) {
        int4 d4 = ((const int4*)edst)[t];
        int dd[4] = {d4.x, d4.y, d4.z, d4.w};
        #pragma unroll
        for (int j = 0; j < 4; j++) {
            if (g_m2b[dd[j]]) {
                int e = t * 4 + j;
                g_e2[atomicAdd(&g_cnt[0], 1)] = e;
                int s = esrc[e];
                if (atomicExch(&g_m1[s], 1) == 0) {
                    g_m1b[s] = 1;
                    g_s1[atomicAdd(&g_cnt[4], 1)] = s;
                    zero_row_h1(s);
                }
                if (atomicExch(&g_m0[s], 1) == 0) {
                    g_m0b[s] = 1;
                    g_s0[atomicAdd(&g_cnt[3], 1)] = s;
                    zero_row_h0(s);
                }
            }
        }
    }
    gsync();

    // ---------- phase 2: scan1 (E1 = dst in S1; grow S0) ----------
    for (int t = gt; t < EE / 4; t += NT) {
        int4 d4 = ((const int4*)edst)[t];
        int dd[4] = {d4.x, d4.y, d4.z, d4.w};
        #pragma unroll
        for (int j = 0; j < 4; j++) {
            if (g_m1b[dd[j]]) {
                int e = t * 4 + j;
                g_e1[atomicAdd(&g_cnt[1], 1)] = e;
                int s = esrc[e];
                if (atomicExch(&g_m0[s], 1) == 0) {
                    g_m0b[s] = 1;
                    g_s0[atomicAdd(&g_cnt[3], 1)] = s;
                    zero_row_h0(s);
                }
            }
        }
    }
    gsync();

    // ---------- phase 3: scan0 (E0 = dst in S0) ----------
    for (int t = gt; t < EE / 4; t += NT) {
        int4 d4 = ((const int4*)edst)[t];
        int dd[4] = {d4.x, d4.y, d4.z, d4.w};
        #pragma unroll
        for (int j = 0; j < 4; j++) {
            if (g_m0b[dd[j]]) g_e0[atomicAdd(&g_cnt[2], 1)] = t * 4 + j;
        }
    }
    gsync();

    // ---------- phase 4: edge MLP -> h0 (8 edges/block/pass; 256 thr = 2x128) ----------
    {
        int cntE0 = *(volatile int*)&g_cnt[2];
        int o = tid & 127, half = tid >> 7;
        for (int base = bid * 8; base < cntE0; base += GRID * 8) {
            int ne = min(8, cntE0 - base);
            if (tid < ne) {
                int e = g_e0[base + tid];
                int s = esrc[e];
                ss8[tid] = s; ds8[tid] = edst[e]; sea8[tid] = eattr[e];
                sent8[tid] = (int)x[s * 36 + 35];
            }
            __syncthreads();
            for (int idx = tid; idx < 52 * 8; idx += TPB) {
                int j = idx >> 3, e = idx & 7;
                float v = 0.f;
                if (e < ne) {
                    if (j < 35)      v = x[ss8[e] * 36 + j];
                    else if (j < 51) v = emb[sent8[e] * 16 + (j - 35)];
                    else             v = sea8[e];
                }
                sint[j][e] = v;
            }
            __syncthreads();
            float acc[4];
            {
                float b = b1[o];
                acc[0] = b; acc[1] = b; acc[2] = b; acc[3] = b;
            }
            for (int j = 0; j < 52; j++) {
                float w = w1[j * 128 + o];
                float4 a = *(float4*)&sint[j][half * 4];
                acc[0] += a.x * w; acc[1] += a.y * w; acc[2] += a.z * w; acc[3] += a.w * w;
            }
            #pragma unroll
            for (int e = 0; e < 4; e++) szt[o][half * 4 + e] = fmaxf(acc[e], 0.f);
            __syncthreads();
            float acc2[4];
            {
                float b = bh[o];
                acc2[0] = b; acc2[1] = b; acc2[2] = b; acc2[3] = b;
            }
            #pragma unroll 4
            for (int j = 0; j < 128; j++) {
                float w = wh[j * 128 + o];
                float4 a = *(float4*)&szt[j][half * 4];
                acc2[0] += a.x * w; acc2[1] += a.y * w; acc2[2] += a.z * w; acc2[3] += a.w * w;
            }
            #pragma unroll
            for (int e = 0; e < 4; e++) {
                int ee = half * 4 + e;
                if (ee < ne) atomicAdd(&g_h0[ds8[ee] * 128 + o], fmaxf(acc2[e], 0.f));
            }
            __syncthreads();
        }
    }
    gsync();

    // ---------- phase 5: qkv layer 1 (over S0) ----------
    qkv_phase<128>(g_h0, g_s0, *(volatile int*)&g_cnt[3],
                   q1w, q1b, k1w, k1b, v1w, v1b, hrt, ns4, bid, tid);
    gsync();

    // ---------- phase 6: layer-1 alpha + segment max ----------
    {
        int cnt4 = *(volatile int*)&g_cnt[1] * 4;
        for (int t = gt; t < cnt4; t += NT) {
            int i = t >> 2, h = t & 3;
            int e = g_e1[i];
            int s = esrc[e], d = edst[e];
            float ea = eattr[e];
            const float4* qp = (const float4*)(g_q + d * 256 + h * 64);
            const float4* kp = (const float4*)(g_k + s * 256 + h * 64);
            const float4* ep = (const float4*)(e1w + h * 64);
            float dot = 0.f;
            #pragma unroll
            for (int c = 0; c < 16; c++) {
                float4 q = qp[c], k = kp[c], w = ep[c];
                dot += q.x * (k.x + ea * w.x) + q.y * (k.y + ea * w.y)
                     + q.z * (k.z + ea * w.z) + q.w * (k.w + ea * w.w);
            }
            float a = dot * 0.125f;
            g_alpha[t] = a;
            atomicMaxF(&g_amax[d * 4 + h], a);
        }
    }
    gsync();

    // ---------- phase 7: layer-1 exp + sum + unnormalized message ----------
    {
        int cntE1 = *(volatile int*)&g_cnt[1];
        int h = tid >> 6;
        for (int i = bid; i < cntE1; i += GRID) {
            int e = g_e1[i];
            int s = esrc[e], d = edst[e];
            float ea = eattr[e];
            float ex = expf(g_alpha[i * 4 + h] - g_amax[d * 4 + h]);
            if ((tid & 63) == 0) atomicAdd(&g_asum[d * 4 + h], ex);
            atomicAdd(&g_h1[d * 256 + tid], (g_v[s * 256 + tid] + ea * e1w[tid]) * ex);
        }
    }
    gsync();

    // ---------- phase 8: finalize layer 1 ----------
    {
        int cntS1 = *(volatile int*)&g_cnt[4];
        for (int i = bid; i < cntS1; i += GRID) {
            int n = g_s1[i];
            if (tid < 128) hr[tid] = g_h0[n * 128 + tid];
            __syncthreads();
            int h = tid >> 6;
            float a = g_h1[n * 256 + tid] / (g_asum[n * 4 + h] + 1e-16f) + s1b[tid];
            #pragma unroll 4
            for (int j = 0; j < 128; j++) a += hr[j] * s1w[j * 256 + tid];
            g_h1[n * 256 + tid] = fmaxf(a, 0.f);
            __syncthreads();
        }
    }
    gsync();

    // ---------- phase 9: qkv layer 2 (over S1) ----------
    qkv_phase<256>(g_h1, g_s1, *(volatile int*)&g_cnt[4],
                   q2w, q2b, k2w, k2b, v2w, v2b, hrt, ns4, bid, tid);
    gsync();

    // ---------- phase 10: layer-2 attention + output (blocks 0..7) ----------
    if (bid < 8) {
        int b = bid;
        int n = b * NPGS + sa[b];
        int cnt = *(volatile int*)&g_cnt[0]; if (cnt > 256) cnt = 256;
        if (tid < cnt) {
            int e = g_e2[tid];
            sd_all[tid] = edst[e]; ss_all[tid] = esrc[e]; sea_all[tid] = eattr[e];
        }
        __syncthreads();
        if (tid == 0) {
            int p = 0;
            for (int i = 0; i < cnt; i++)
                if ((sd_all[i] >> 13) == b && p < 64) { ssrc[p] = ss_all[i]; seaa[p] = sea_all[i]; p++; }
            ne_sh = p;
        }
        __syncthreads();
        int ne = ne_sh;
        int wid = tid >> 5, lane = tid & 31;
        for (int p = wid; p < ne * 4; p += 8) {
            int k = p >> 2, h = p & 3;
            int s = ssrc[k]; float ea = seaa[k];
            float d0 = 0.f;
            #pragma unroll
            for (int c0 = 0; c0 < 2; c0++) {
                int c = lane + c0 * 32;
                d0 += g_q[n * 256 + h * 64 + c] * (g_k[s * 256 + h * 64 + c] + ea * e2w[h * 64 + c]);
            }
            #pragma unroll
            for (int o = 16; o; o >>= 1) d0 += __shfl_xor_sync(0xffffffffu, d0, o);
            if (lane == 0) sal[h][k] = d0 * 0.125f;
        }
        __syncthreads();
        if (tid < 4) {
            float m = NEG_INF;
            for (int k = 0; k < ne; k++) m = fmaxf(m, sal[tid][k]);
            float s = 0.f;
            for (int k = 0; k < ne; k++) { float ex = expf(sal[tid][k] - m); sal[tid][k] = ex; s += ex; }
            float inv = 1.f / (s + 1e-16f);
            for (int k = 0; k < ne; k++) sal[tid][k] *= inv;
        }
        __syncthreads();
        int h = tid >> 6;
        float acc = 0.f;
        for (int k = 0; k < ne; k++)
            acc += (g_v[ssrc[k] * 256 + tid] + seaa[k] * e2w[tid]) * sal[h][k];
        hr[tid] = g_h1[n * 256 + tid];
        __syncthreads();
        float o = acc + s2b[tid];
        #pragma unroll 4
        for (int j = 0; j < 256; j++) o += hr[j] * s2w[j * 256 + tid];
        out[b * 256 + tid] = fmaxf(o, 0.f);
    }
}

// ---------------- launch ----------------
extern "C" void kernel_launch(void* const* d_in, const int* in_sizes, int n_in,
                              void* d_out, int out_size) {
    const float* x     = (const float*)d_in[0];
    const int*   esrc  = (const int*)d_in[1];
    const int*   edst  = (const int*)d_in[2];
    const float* eattr = (const float*)d_in[3];
    const int*   aid   = (const int*)d_in[4];
    const float* emb   = (const float*)d_in[5];
    const float* w1    = (const float*)d_in[6];
    const float* b1    = (const float*)d_in[7];
    const float* wh    = (const float*)d_in[8];
    const float* bh    = (const float*)d_in[9];
    const float* q1w = (const float*)d_in[10], *q1b = (const float*)d_in[11];
    const float* k1w = (const float*)d_in[12], *k1b = (const float*)d_in[13];
    const float* v1w = (const float*)d_in[14], *v1b = (const float*)d_in[15];
    const float* e1w = (const float*)d_in[16];
    const float* s1w = (const float*)d_in[17], *s1b = (const float*)d_in[18];
    const float* q2w = (const float*)d_in[19], *q2b = (const float*)d_in[20];
    const float* k2w = (const float*)d_in[21], *k2b = (const float*)d_in[22];
    const float* v2w = (const float*)d_in[23], *v2b = (const float*)d_in[24];
    const float* e2w = (const float*)d_in[25];
    const float* s2w = (const float*)d_in[26], *s2b = (const float*)d_in[27];
    float* out = (float*)d_out;

    k_mega<<<GRID, TPB>>>(x, esrc, edst, eattr, aid, emb, w1, b1, wh, bh,
                          q1w, q1b, k1w, k1b, v1w, v1b, e1w, s1w, s1b,
                          q2w, q2b, k2w, k2b, v2w, v2b, e2w, s2w, s2b, out);
}

// round 5
// speedup vs baseline: 2.1269x; 1.4596x over previous
#include <cuda_runtime.h>
#include <math.h>

#define NN 65536
#define EE 262144
#define NPGS 8192
#define GRID 148
#define TPB 256
#define NT (GRID * TPB)
#define NEG_INF __int_as_float(0xff800000)

// ---------------- scratch (device globals; 16B-aligned for vector casts) ----------------
__device__ __align__(16) int            g_m1[NN], g_m0[NN];
__device__ __align__(16) unsigned char  g_m1b[NN], g_m0b[NN];
__device__ __align__(16) int   g_e0[EE], g_e1[EE], g_e2[EE];
__device__ __align__(16) int   g_s0[NN], g_s1[NN];
__device__ __align__(16) int   g_cnt[8];     // 0:nE2 1:nE1 2:nE0 3:nS0 4:nS1
__device__ __align__(16) float g_h0[NN * 128];
__device__ __align__(16) float g_h1[NN * 256];   // layer-1 message numerator
__device__ __align__(16) float g_q[NN * 256];
__device__ __align__(16) float g_k[NN * 256];
__device__ __align__(16) float g_v[NN * 256];
__device__ __align__(16) float g_t1[NN * 256];   // skip GEMV, indexed by S1 list position
__device__ __align__(16) float g_t2[8 * 256];
__device__ __align__(16) float g_amax[NN * 4];
__device__ __align__(16) float g_asum[NN * 4];
__device__ __align__(16) float g_alpha[EE * 4];

// software grid barrier (generation-based; persists across graph replays)
__device__ unsigned          g_bar_cnt;
__device__ volatile unsigned g_bar_gen;

__device__ __forceinline__ void gsync() {
    __syncthreads();
    if (threadIdx.x == 0) {
        __threadfence();
        unsigned gen = g_bar_gen;
        if (atomicAdd(&g_bar_cnt, 1u) == GRID - 1) {
            g_bar_cnt = 0;
            __threadfence();
            g_bar_gen = gen + 1;
        } else {
            while (g_bar_gen == gen) __nanosleep(32);
            __threadfence();
        }
    }
    __syncthreads();
}

__device__ __forceinline__ void atomicMaxF(float* a, float v) {
    if (v >= 0.0f) atomicMax((int*)a, __float_as_int(v));
    else           atomicMin((unsigned int*)a, __float_as_uint(v));
}

__device__ __forceinline__ void zero_row_h1(int n) {
    float4 z = make_float4(0.f, 0.f, 0.f, 0.f);
    float4* p = (float4*)&g_h1[n * 256];
    #pragma unroll 8
    for (int q = 0; q < 64; q++) p[q] = z;
    ((float4*)&g_amax[n * 4])[0] = make_float4(NEG_INF, NEG_INF, NEG_INF, NEG_INF);
    ((float4*)&g_asum[n * 4])[0] = z;
}
__device__ __forceinline__ void zero_row_h0(int n) {
    float4 z = make_float4(0.f, 0.f, 0.f, 0.f);
    float4* p = (float4*)&g_h0[n * 128];
    #pragma unroll 8
    for (int q = 0; q < 32; q++) p[q] = z;
}

// h1 final value computed on the fly: relu(msg_numerator/asum + t1)
__device__ __forceinline__ float h1val(int n, int i, int j) {
    return fmaxf(g_h1[n * 256 + j] / (g_asum[n * 4 + (j >> 6)] + 1e-16f)
                 + g_t1[i * 256 + j], 0.f);
}

// ==================== single persistent megakernel ====================
__global__ void __launch_bounds__(TPB)
k_mega(const float* __restrict__ x, const int* __restrict__ esrc,
       const int* __restrict__ edst, const float* __restrict__ eattr,
       const int* __restrict__ aid, const float* __restrict__ emb,
       const float* __restrict__ w1, const float* __restrict__ b1,
       const float* __restrict__ wh, const float* __restrict__ bh,
       const float* __restrict__ q1w, const float* __restrict__ q1b,
       const float* __restrict__ k1w, const float* __restrict__ k1b,
       const float* __restrict__ v1w, const float* __restrict__ v1b,
       const float* __restrict__ e1w,
       const float* __restrict__ s1w, const float* __restrict__ s1b,
       const float* __restrict__ q2w, const float* __restrict__ q2b,
       const float* __restrict__ k2w, const float* __restrict__ k2b,
       const float* __restrict__ v2w, const float* __restrict__ v2b,
       const float* __restrict__ e2w,
       const float* __restrict__ s2w, const float* __restrict__ s2b,
       float* __restrict__ out) {
    __shared__ int   sa[8];
    __shared__ __align__(16) float sint[8][52];
    __shared__ __align__(16) float szt[8][128];
    __shared__ int   ss8[8], ds8[8], sent8[8];
    __shared__ float sea8[8];
    __shared__ __align__(16) float hrowA[2][128];
    __shared__ __align__(16) float hq1[4][128];
    __shared__ __align__(16) float hrowB[2][256];
    __shared__ __align__(16) float hq2[4][256];
    __shared__ int   nsA[2], niA[2], nsB[4];
    __shared__ int   sd_all[256], ss_all[256];
    __shared__ float sea_all[256];
    __shared__ int   ssrc[64];
    __shared__ float seaa[64];
    __shared__ float sal[4][64];
    __shared__ int   ne_sh;

    int tid = threadIdx.x, bid = blockIdx.x;
    int gt  = bid * TPB + tid;

    if (tid < 8) sa[tid] = aid[tid];
    __syncthreads();

    // ---------- phase 0: reset + seed ----------
    if (gt < NN / 4) {
        int base = gt * 4;
        int a = sa[base >> 13];
        int4 v;
        v.x = ((base     & 8191) == a);
        v.y = (((base+1) & 8191) == a);
        v.z = (((base+2) & 8191) == a);
        v.w = (((base+3) & 8191) == a);
        ((int4*)g_m1)[gt] = v;
        ((int4*)g_m0)[gt] = v;
    }
    if (gt < NN / 16) {
        int base = gt * 16;
        int a = sa[base >> 13];
        unsigned int w[4];
        #pragma unroll
        for (int g = 0; g < 4; g++) {
            unsigned int acc = 0;
            #pragma unroll
            for (int bb = 0; bb < 4; bb++) {
                int idx = base + g * 4 + bb;
                acc |= (((idx & 8191) == a) ? 1u : 0u) << (8 * bb);
            }
            w[g] = acc;
        }
        uint4 val = make_uint4(w[0], w[1], w[2], w[3]);
        ((uint4*)g_m1b)[gt] = val;
        ((uint4*)g_m0b)[gt] = val;
    }
    if (gt == 0) { g_cnt[0] = 0; g_cnt[1] = 0; g_cnt[2] = 0; g_cnt[3] = 8; g_cnt[4] = 8; }
    if (gt < 8) {
        int n = gt * NPGS + sa[gt];
        g_s0[gt] = n; g_s1[gt] = n;
        zero_row_h0(n);
        zero_row_h1(n);
    }
    gsync();

    // ---------- phase 1: scan2 (dst in S2 tested arithmetically; grow S1, S0) ----------
    for (int t = gt; t < EE / 4; t += NT) {
        int4 d4 = ((const int4*)edst)[t];
        int dd[4] = {d4.x, d4.y, d4.z, d4.w};
        #pragma unroll
        for (int j = 0; j < 4; j++) {
            int d = dd[j];
            if ((d & 8191) == sa[d >> 13]) {
                int e = t * 4 + j;
                g_e2[atomicAdd(&g_cnt[0], 1)] = e;
                int s = esrc[e];
                if (atomicExch(&g_m1[s], 1) == 0) {
                    g_m1b[s] = 1;
                    g_s1[atomicAdd(&g_cnt[4], 1)] = s;
                    zero_row_h1(s);
                }
                if (atomicExch(&g_m0[s], 1) == 0) {
                    g_m0b[s] = 1;
                    g_s0[atomicAdd(&g_cnt[3], 1)] = s;
                    zero_row_h0(s);
                }
            }
        }
    }
    gsync();

    // ---------- phase 2: scan1 (dst in S1; grow S0) ----------
    for (int t = gt; t < EE / 4; t += NT) {
        int4 d4 = ((const int4*)edst)[t];
        int dd[4] = {d4.x, d4.y, d4.z, d4.w};
        #pragma unroll
        for (int j = 0; j < 4; j++) {
            if (g_m1b[dd[j]]) {
                int e = t * 4 + j;
                g_e1[atomicAdd(&g_cnt[1], 1)] = e;
                int s = esrc[e];
                if (atomicExch(&g_m0[s], 1) == 0) {
                    g_m0b[s] = 1;
                    g_s0[atomicAdd(&g_cnt[3], 1)] = s;
                    zero_row_h0(s);
                }
            }
        }
    }
    gsync();

    // ---------- phase 3: scan0 (dst in S0) ----------
    for (int t = gt; t < EE / 4; t += NT) {
        int4 d4 = ((const int4*)edst)[t];
        int dd[4] = {d4.x, d4.y, d4.z, d4.w};
        #pragma unroll
        for (int j = 0; j < 4; j++) {
            if (g_m0b[dd[j]]) g_e0[atomicAdd(&g_cnt[2], 1)] = t * 4 + j;
        }
    }
    gsync();

    // ---------- phase 4: edge MLP -> h0 (8 edges/pass; thread = slot x 4-col group) ----------
    {
        int cntE0 = *(volatile int*)&g_cnt[2];
        int slot = tid >> 5;            // 8 edge slots x 32 threads
        int c4   = (tid & 31) * 4;      // 128 cols / 4
        for (int base = bid * 8; base < cntE0; base += GRID * 8) {
            int ne = min(8, cntE0 - base);
            if (tid < ne) {
                int e = g_e0[base + tid];
                int s = esrc[e];
                ss8[tid] = s; ds8[tid] = edst[e]; sea8[tid] = eattr[e];
                sent8[tid] = (int)x[s * 36 + 35];
            }
            __syncthreads();
            for (int idx = tid; idx < 8 * 52; idx += TPB) {
                int sl = idx / 52, j = idx % 52;
                float v = 0.f;
                if (sl < ne) {
                    if (j < 35)      v = x[ss8[sl] * 36 + j];
                    else if (j < 51) v = emb[sent8[sl] * 16 + (j - 35)];
                    else             v = sea8[sl];
                }
                sint[sl][j] = v;
            }
            __syncthreads();
            float4 acc = *(const float4*)&b1[c4];
            #pragma unroll 4
            for (int j = 0; j < 52; j++) {
                float4 w = *(const float4*)&w1[j * 128 + c4];
                float h = sint[slot][j];
                acc.x += h * w.x; acc.y += h * w.y; acc.z += h * w.z; acc.w += h * w.w;
            }
            acc.x = fmaxf(acc.x, 0.f); acc.y = fmaxf(acc.y, 0.f);
            acc.z = fmaxf(acc.z, 0.f); acc.w = fmaxf(acc.w, 0.f);
            *(float4*)&szt[slot][c4] = acc;
            __syncthreads();
            float4 a2 = *(const float4*)&bh[c4];
            #pragma unroll 8
            for (int j = 0; j < 128; j++) {
                float4 w = *(const float4*)&wh[j * 128 + c4];
                float h = szt[slot][j];
                a2.x += h * w.x; a2.y += h * w.y; a2.z += h * w.z; a2.w += h * w.w;
            }
            if (slot < ne) {
                float* hp = &g_h0[ds8[slot] * 128 + c4];
                atomicAdd(hp + 0, fmaxf(a2.x, 0.f));
                atomicAdd(hp + 1, fmaxf(a2.y, 0.f));
                atomicAdd(hp + 2, fmaxf(a2.z, 0.f));
                atomicAdd(hp + 3, fmaxf(a2.w, 0.f));
            }
            __syncthreads();
        }
    }
    gsync();

    // ---------- phase 5: k,v over S0 (blocks 0-127) || q over S1 (blocks 128-147) ----------
    {
        int cntS0 = *(volatile int*)&g_cnt[3];
        int cntS1 = *(volatile int*)&g_cnt[4];
        if (bid < 128) {
            int slot = tid >> 7;            // 2 nodes/pass
            int m    = (tid >> 6) & 1;      // 0=k, 1=v
            int c4   = (tid & 63) * 4;
            const float* W  = m ? v1w : k1w;
            const float* Bb = m ? v1b : k1b;
            for (int base = bid * 2; base < cntS0; base += 128 * 2) {
                if (tid < 2) nsA[tid] = g_s0[min(base + tid, cntS0 - 1)];
                __syncthreads();
                for (int idx = tid; idx < 256; idx += TPB)
                    hrowA[idx >> 7][idx & 127] = g_h0[nsA[idx >> 7] * 128 + (idx & 127)];
                __syncthreads();
                float4 acc = *(const float4*)&Bb[c4];
                #pragma unroll 8
                for (int j = 0; j < 128; j++) {
                    float4 w = *(const float4*)&W[j * 256 + c4];
                    float h = hrowA[slot][j];
                    acc.x += h * w.x; acc.y += h * w.y; acc.z += h * w.z; acc.w += h * w.w;
                }
                if (base + slot < cntS0)
                    *(float4*)((m ? g_v : g_k) + nsA[slot] * 256 + c4) = acc;
                __syncthreads();
            }
        } else {
            int bq = bid - 128;             // 0..19
            int slot = tid >> 6;            // 4 nodes/pass
            int c4 = (tid & 63) * 4;
            for (int base = bq * 4; base < cntS1; base += 20 * 4) {
                if (tid < 4) nsB[tid] = g_s1[min(base + tid, cntS1 - 1)];
                __syncthreads();
                for (int idx = tid; idx < 512; idx += TPB)
                    hq1[idx >> 7][idx & 127] = g_h0[nsB[idx >> 7] * 128 + (idx & 127)];
                __syncthreads();
                float4 acc = *(const float4*)&q1b[c4];
                #pragma unroll 8
                for (int j = 0; j < 128; j++) {
                    float4 w = *(const float4*)&q1w[j * 256 + c4];
                    float h = hq1[slot][j];
                    acc.x += h * w.x; acc.y += h * w.y; acc.z += h * w.z; acc.w += h * w.w;
                }
                if (base + slot < cntS1)
                    *(float4*)&g_q[nsB[slot] * 256 + c4] = acc;
                __syncthreads();
            }
        }
    }
    gsync();

    // ---------- phase 6: alpha+amax over E1 (blocks 0-15) || t1 = h0@s1w+s1b (blocks 16+) ----
    {
        int cntE1 = *(volatile int*)&g_cnt[1];
        int cntS1 = *(volatile int*)&g_cnt[4];
        if (bid < 16) {
            int cnt4 = cntE1 * 4;
            for (int t = bid * TPB + tid; t < cnt4; t += 16 * TPB) {
                int i = t >> 2, h = t & 3;
                int e = g_e1[i];
                int s = esrc[e], d = edst[e];
                float ea = eattr[e];
                const float4* qp = (const float4*)(g_q + d * 256 + h * 64);
                const float4* kp = (const float4*)(g_k + s * 256 + h * 64);
                const float4* ep = (const float4*)(e1w + h * 64);
                float dot = 0.f;
                #pragma unroll
                for (int c = 0; c < 16; c++) {
                    float4 q = qp[c], k = kp[c], w = ep[c];
                    dot += q.x * (k.x + ea * w.x) + q.y * (k.y + ea * w.y)
                         + q.z * (k.z + ea * w.z) + q.w * (k.w + ea * w.w);
                }
                float a = dot * 0.125f;
                g_alpha[t] = a;
                atomicMaxF(&g_amax[d * 4 + h], a);
            }
        } else {
            int bt = bid - 16;              // 0..131
            int slot = tid >> 6;
            int c4 = (tid & 63) * 4;
            for (int base = bt * 4; base < cntS1; base += 132 * 4) {
                if (tid < 4) nsB[tid] = g_s1[min(base + tid, cntS1 - 1)];
                __syncthreads();
                for (int idx = tid; idx < 512; idx += TPB)
                    hq1[idx >> 7][idx & 127] = g_h0[nsB[idx >> 7] * 128 + (idx & 127)];
                __syncthreads();
                float4 acc = *(const float4*)&s1b[c4];
                #pragma unroll 8
                for (int j = 0; j < 128; j++) {
                    float4 w = *(const float4*)&s1w[j * 256 + c4];
                    float h = hq1[slot][j];
                    acc.x += h * w.x; acc.y += h * w.y; acc.z += h * w.z; acc.w += h * w.w;
                }
                if (base + slot < cntS1)
                    *(float4*)&g_t1[(base + slot) * 256 + c4] = acc;
                __syncthreads();
            }
        }
    }
    gsync();

    // ---------- phase 7: exp + sum + unnormalized message -> g_h1 ----------
    {
        int cntE1 = *(volatile int*)&g_cnt[1];
        int h = tid >> 6;
        for (int i = bid; i < cntE1; i += GRID) {
            int e = g_e1[i];
            int s = esrc[e], d = edst[e];
            float ea = eattr[e];
            float ex = expf(g_alpha[i * 4 + h] - g_amax[d * 4 + h]);
            if ((tid & 63) == 0) atomicAdd(&g_asum[d * 4 + h], ex);
            atomicAdd(&g_h1[d * 256 + tid], (g_v[s * 256 + tid] + ea * e1w[tid]) * ex);
        }
    }
    gsync();

    // ---------- phase 8: k2,v2 over S1 (blocks 0-99) || q2 over seeds (100-101)
    //                      || t2 = h1@s2w+s2b over seeds (102-103) ----------
    {
        int cntS1 = *(volatile int*)&g_cnt[4];
        if (bid < 100) {
            int slot = tid >> 7;
            int m    = (tid >> 6) & 1;
            int c4   = (tid & 63) * 4;
            const float* W  = m ? v2w : k2w;
            const float* Bb = m ? v2b : k2b;
            for (int base = bid * 2; base < cntS1; base += 100 * 2) {
                if (tid < 2) {
                    int ii = min(base + tid, cntS1 - 1);
                    niA[tid] = ii; nsA[tid] = g_s1[ii];
                }
                __syncthreads();
                for (int idx = tid; idx < 512; idx += TPB) {
                    int sl = idx >> 8, j = idx & 255;
                    hrowB[sl][j] = h1val(nsA[sl], niA[sl], j);
                }
                __syncthreads();
                float4 acc = *(const float4*)&Bb[c4];
                #pragma unroll 8
                for (int j = 0; j < 256; j++) {
                    float4 w = *(const float4*)&W[j * 256 + c4];
                    float h = hrowB[slot][j];
                    acc.x += h * w.x; acc.y += h * w.y; acc.z += h * w.z; acc.w += h * w.w;
                }
                if (base + slot < cntS1)
                    *(float4*)((m ? g_v : g_k) + nsA[slot] * 256 + c4) = acc;
                __syncthreads();
            }
        } else if (bid < 102) {
            int bq = bid - 100;             // 0..1 -> seeds 0-3 / 4-7
            int slot = tid >> 6;
            int c4 = (tid & 63) * 4;
            int i = bq * 4 + slot;          // seed index = S1 list position
            int n = g_s1[i];
            for (int idx = tid; idx < 1024; idx += TPB) {
                int sl = idx >> 8, j = idx & 255;
                hq2[sl][j] = h1val(g_s1[bq * 4 + sl], bq * 4 + sl, j);
            }
            __syncthreads();
            float4 acc = *(const float4*)&q2b[c4];
            #pragma unroll 8
            for (int j = 0; j < 256; j++) {
                float4 w = *(const float4*)&q2w[j * 256 + c4];
                float h = hq2[slot][j];
                acc.x += h * w.x; acc.y += h * w.y; acc.z += h * w.z; acc.w += h * w.w;
            }
            *(float4*)&g_q[n * 256 + c4] = acc;
        } else if (bid < 104) {
            int bq = bid - 102;
            int slot = tid >> 6;
            int c4 = (tid & 63) * 4;
            int i = bq * 4 + slot;
            for (int idx = tid; idx < 1024; idx += TPB) {
                int sl = idx >> 8, j = idx & 255;
                hq2[sl][j] = h1val(g_s1[bq * 4 + sl], bq * 4 + sl, j);
            }
            __syncthreads();
            float4 acc = *(const float4*)&s2b[c4];
            #pragma unroll 8
            for (int j = 0; j < 256; j++) {
                float4 w = *(const float4*)&s2w[j * 256 + c4];
                float h = hq2[slot][j];
                acc.x += h * w.x; acc.y += h * w.y; acc.z += h * w.z; acc.w += h * w.w;
            }
            *(float4*)&g_t2[i * 256 + c4] = acc;
        }
    }
    gsync();

    // ---------- phase 9: layer-2 attention + output (blocks 0..7) ----------
    if (bid < 8) {
        int b = bid;
        int n = b * NPGS + sa[b];
        int cnt = *(volatile int*)&g_cnt[0]; if (cnt > 256) cnt = 256;
        if (tid < cnt) {
            int e = g_e2[tid];
            sd_all[tid] = edst[e]; ss_all[tid] = esrc[e]; sea_all[tid] = eattr[e];
        }
        __syncthreads();
        if (tid == 0) {
            int p = 0;
            for (int i = 0; i < cnt; i++)
                if ((sd_all[i] >> 13) == b && p < 64) { ssrc[p] = ss_all[i]; seaa[p] = sea_all[i]; p++; }
            ne_sh = p;
        }
        __syncthreads();
        int ne = ne_sh;
        int wid = tid >> 5, lane = tid & 31;
        for (int p = wid; p < ne * 4; p += 8) {
            int k = p >> 2, h = p & 3;
            int s = ssrc[k]; float ea = seaa[k];
            float d0 = 0.f;
            #pragma unroll
            for (int c0 = 0; c0 < 2; c0++) {
                int c = lane + c0 * 32;
                d0 += g_q[n * 256 + h * 64 + c] * (g_k[s * 256 + h * 64 + c] + ea * e2w[h * 64 + c]);
            }
            #pragma unroll
            for (int o = 16; o; o >>= 1) d0 += __shfl_xor_sync(0xffffffffu, d0, o);
            if (lane == 0) sal[h][k] = d0 * 0.125f;
        }
        __syncthreads();
        if (tid < 4) {
            float m = NEG_INF;
            for (int k = 0; k < ne; k++) m = fmaxf(m, sal[tid][k]);
            float s = 0.f;
            for (int k = 0; k < ne; k++) { float ex = expf(sal[tid][k] - m); sal[tid][k] = ex; s += ex; }
            float inv = 1.f / (s + 1e-16f);
            for (int k = 0; k < ne; k++) sal[tid][k] *= inv;
        }
        __syncthreads();
        int h = tid >> 6;
        float acc = 0.f;
        for (int k = 0; k < ne; k++)
            acc += (g_v[ssrc[k] * 256 + tid] + seaa[k] * e2w[tid]) * sal[h][k];
        out[b * 256 + tid] = fmaxf(acc + g_t2[b * 256 + tid], 0.f);
    }
}

// ---------------- launch ----------------
extern "C" void kernel_launch(void* const* d_in, const int* in_sizes, int n_in,
                              void* d_out, int out_size) {
    const float* x     = (const float*)d_in[0];
    const int*   esrc  = (const int*)d_in[1];
    const int*   edst  = (const int*)d_in[2];
    const float* eattr = (const float*)d_in[3];
    const int*   aid   = (const int*)d_in[4];
    const float* emb   = (const float*)d_in[5];
    const float* w1    = (const float*)d_in[6];
    const float* b1    = (const float*)d_in[7];
    const float* wh    = (const float*)d_in[8];
    const float* bh    = (const float*)d_in[9];
    const float* q1w = (const float*)d_in[10], *q1b = (const float*)d_in[11];
    const float* k1w = (const float*)d_in[12], *k1b = (const float*)d_in[13];
    const float* v1w = (const float*)d_in[14], *v1b = (const float*)d_in[15];
    const float* e1w = (const float*)d_in[16];
    const float* s1w = (const float*)d_in[17], *s1b = (const float*)d_in[18];
    const float* q2w = (const float*)d_in[19], *q2b = (const float*)d_in[20];
    const float* k2w = (const float*)d_in[21], *k2b = (const float*)d_in[22];
    const float* v2w = (const float*)d_in[23], *v2b = (const float*)d_in[24];
    const float* e2w = (const float*)d_in[25];
    const float* s2w = (const float*)d_in[26], *s2b = (const float*)d_in[27];
    float* out = (float*)d_out;

    k_mega<<<GRID, TPB>>>(x, esrc, edst, eattr, aid, emb, w1, b1, wh, bh,
                          q1w, q1b, k1w, k1b, v1w, v1b, e1w, s1w, s1b,
                          q2w, q2b, k2w, k2b, v2w, v2b, e2w, s2w, s2b, out);
}